// round 1
// baseline (speedup 1.0000x reference)
#include <cuda_runtime.h>
#include <cuda_bf16.h>
#include <math.h>

// ---------------------------------------------------------------------------
// Problem constants
// ---------------------------------------------------------------------------
#define T_STEPS 512          // L*N = 64*8
#define HDIM    1024
#define GDIM    4096         // 4*H
#define VOCAB   32000
#define NCTA    128          // recurrence CTAs (<= 148 SMs, 1 CTA/SM -> co-resident)

// ---------------------------------------------------------------------------
// Device scratch (static allocation is allowed; cudaMalloc is not)
// ---------------------------------------------------------------------------
__device__ float    g_seq[T_STEPS * HDIM];     // 2 MB  embedding sequence
__device__ float    g_X  [T_STEPS * GDIM];     // 8 MB  precomputed W_ih@x + biases (reused per layer)
__device__ float    g_H0 [T_STEPS * HDIM];     // 2 MB  layer-0 hidden states
__device__ float    g_H1 [T_STEPS * HDIM];     // 2 MB  layer-1 hidden states
__device__ unsigned g_bar[T_STEPS];            // per-step grid-barrier counters

// ---------------------------------------------------------------------------
// f32x2 packed-FMA helpers (sm_100+)
// ---------------------------------------------------------------------------
__device__ __forceinline__ unsigned long long pack2(float lo, float hi) {
    unsigned long long r;
    asm("mov.b64 %0, {%1, %2};" : "=l"(r) : "f"(lo), "f"(hi));
    return r;
}
__device__ __forceinline__ void unpack2(unsigned long long v, float& lo, float& hi) {
    asm("mov.b64 {%0, %1}, %2;" : "=f"(lo), "=f"(hi) : "l"(v));
}
__device__ __forceinline__ unsigned long long fma2(unsigned long long a,
                                                   unsigned long long b,
                                                   unsigned long long c) {
    unsigned long long d;
    asm("fma.rn.f32x2 %0, %1, %2, %3;" : "=l"(d) : "l"(a), "l"(b), "l"(c));
    return d;
}

// ---------------------------------------------------------------------------
// Embedding gather: seq[t] = emb[x[n, l]],  t = l*8 + n
// ---------------------------------------------------------------------------
__global__ void embed_kernel(const int* __restrict__ x, const float* __restrict__ emb) {
    int t = blockIdx.x;             // 0..511
    int n = t & 7;                  // t % 8
    int l = t >> 3;                 // t / 8
    int tok = x[n * 64 + l];
    const float4* src = (const float4*)(emb + (size_t)tok * HDIM);
    ((float4*)(g_seq + (size_t)t * HDIM))[threadIdx.x] = src[threadIdx.x];  // 256 thr * 4 = 1024
}

// ---------------------------------------------------------------------------
// Barrier reset
// ---------------------------------------------------------------------------
__global__ void reset_bar_kernel() {
    g_bar[threadIdx.x] = 0u;        // 512 threads
}

// ---------------------------------------------------------------------------
// NT GEMM:  C[m][n] = dot(A[m,:K], B[n,:K]) + bias1[n] (+ bias2[n])
// A: MxK row-major, B: NxK row-major, C: MxN row-major.
// Tiles 128x128x16, 256 threads, 8x8 per thread, f32x2 packed FMA.
// M,N,K multiples of 128/128/16 (guaranteed by problem shapes).
// ---------------------------------------------------------------------------
__global__ void __launch_bounds__(256, 2) gemm_nt_bias(
    const float* __restrict__ A, const float* __restrict__ B,
    const float* __restrict__ bias1, const float* __restrict__ bias2,
    float* __restrict__ C, int M, int N, int K)
{
    __shared__ float As[16][128];
    __shared__ float Bs[16][128];

    const int tid = threadIdx.x;
    const int tx = tid & 15;        // 0..15 -> n blocks of 8
    const int ty = tid >> 4;        // 0..15 -> m blocks of 8
    const int bm = blockIdx.y * 128;
    const int bn = blockIdx.x * 128;

    unsigned long long acc[8][4];
    #pragma unroll
    for (int i = 0; i < 8; i++)
        #pragma unroll
        for (int j = 0; j < 4; j++) acc[i][j] = 0ull;

    for (int k0 = 0; k0 < K; k0 += 16) {
        // Load 128x16 A-tile and B-tile (transposed into [k][m]) — 2 float4 per thread each
        #pragma unroll
        for (int i = 0; i < 2; i++) {
            int chunk = tid * 2 + i;          // 0..511
            int ar = chunk >> 2;              // 0..127
            int ac = chunk & 3;               // 0..3  (k chunk of 4)
            float4 v = *(const float4*)(A + (size_t)(bm + ar) * K + k0 + ac * 4);
            As[ac * 4 + 0][ar] = v.x; As[ac * 4 + 1][ar] = v.y;
            As[ac * 4 + 2][ar] = v.z; As[ac * 4 + 3][ar] = v.w;
            float4 u = *(const float4*)(B + (size_t)(bn + ar) * K + k0 + ac * 4);
            Bs[ac * 4 + 0][ar] = u.x; Bs[ac * 4 + 1][ar] = u.y;
            Bs[ac * 4 + 2][ar] = u.z; Bs[ac * 4 + 3][ar] = u.w;
        }
        __syncthreads();

        #pragma unroll
        for (int kk = 0; kk < 16; kk++) {
            float4 a0 = *(const float4*)&As[kk][ty * 8];
            float4 a1 = *(const float4*)&As[kk][ty * 8 + 4];
            const unsigned long long* bp = (const unsigned long long*)&Bs[kk][tx * 8];
            unsigned long long b2[4];
            #pragma unroll
            for (int j = 0; j < 4; j++) b2[j] = bp[j];
            float a[8] = {a0.x, a0.y, a0.z, a0.w, a1.x, a1.y, a1.z, a1.w};
            #pragma unroll
            for (int i = 0; i < 8; i++) {
                unsigned long long a2 = pack2(a[i], a[i]);
                #pragma unroll
                for (int j = 0; j < 4; j++) acc[i][j] = fma2(a2, b2[j], acc[i][j]);
            }
        }
        __syncthreads();
    }

    // Epilogue: add bias, store
    #pragma unroll
    for (int i = 0; i < 8; i++) {
        int m = bm + ty * 8 + i;
        float* crow = C + (size_t)m * N + bn + tx * 8;
        #pragma unroll
        for (int j = 0; j < 4; j++) {
            float lo, hi;
            unpack2(acc[i][j], lo, hi);
            int n = bn + tx * 8 + 2 * j;
            lo += bias1[n];
            hi += bias1[n + 1];
            if (bias2) { lo += bias2[n]; hi += bias2[n + 1]; }
            float2 st = make_float2(lo, hi);
            *(float2*)(crow + 2 * j) = st;
        }
    }
}

// ---------------------------------------------------------------------------
// LSTM recurrence (one layer, 512 steps).
// grid = 128 CTAs x 256 threads; CTA c owns h-indices [8c, 8c+8) = 32 gate rows.
// W_hh rows live in SMEM (128 KB). Per step: matvec -> gates -> activations ->
// write 8 h values -> grid barrier -> reload full h.
// SMEM: w_s[32*1024] | h_s[1024] | g_s[32] | xp_s[32]
// ---------------------------------------------------------------------------
#define RECUR_SMEM ((32 * 1024 + 1024 + 32 + 32) * 4)

__global__ void __launch_bounds__(256, 1) lstm_recur_kernel(
    const float* __restrict__ Xpre,      // [512*4096] precomputed ih part + biases
    const float* __restrict__ Whh,       // [4096*1024] this layer's W_hh
    float* __restrict__ Hout,            // [512*1024] per-step hidden
    float* __restrict__ out_h,           // [1024] final h  (may be null)
    float* __restrict__ out_c)           // [1024] final c  (may be null)
{
    extern __shared__ float sm[];
    float* w_s  = sm;                    // 32 rows x 1024
    float* h_s  = sm + 32 * 1024;        // 1024
    float* g_s  = h_s + 1024;            // 32 gate partials (rr = gate*8 + k)
    float* xp_s = g_s + 32;              // 32 prefetched X values

    const int tid  = threadIdx.x;
    const int cta  = blockIdx.x;         // 0..127
    const int hb   = cta * 8;            // first h-index owned
    const int lane = tid & 31;
    const int wrp  = tid >> 5;           // 0..7

    // Preload 32 W_hh rows: rr = gate*8 + k  ->  global row gate*1024 + hb + k
    for (int rr = 0; rr < 32; rr++) {
        int gate = rr >> 3, k = rr & 7;
        const float4* src = (const float4*)(Whh + (size_t)(gate * 1024 + hb + k) * HDIM);
        ((float4*)(w_s + rr * 1024))[tid] = src[tid];
    }
    ((float4*)h_s)[tid] = make_float4(0.f, 0.f, 0.f, 0.f);
    float c_reg = 0.f;
    __syncthreads();

    for (int t = 0; t < T_STEPS; t++) {
        // Prefetch this CTA's 32 X values (latency hidden behind the matvec)
        if (tid < 32)
            xp_s[tid] = Xpre[(size_t)t * GDIM + (tid >> 3) * 1024 + hb + (tid & 7)];

        // Matvec: warp wrp handles rows rr = 4*wrp .. 4*wrp+3 over full h
        float4 hfrag[8];
        #pragma unroll
        for (int j = 0; j < 8; j++) hfrag[j] = ((float4*)h_s)[j * 32 + lane];

        float part[4];
        #pragma unroll
        for (int r = 0; r < 4; r++) {
            const float4* wr = (const float4*)(w_s + (wrp * 4 + r) * 1024);
            float s = 0.f;
            #pragma unroll
            for (int j = 0; j < 8; j++) {
                float4 wv = wr[j * 32 + lane];
                s += wv.x * hfrag[j].x; s += wv.y * hfrag[j].y;
                s += wv.z * hfrag[j].z; s += wv.w * hfrag[j].w;
            }
            part[r] = s;
        }
        #pragma unroll
        for (int r = 0; r < 4; r++) {
            float s = part[r];
            #pragma unroll
            for (int off = 16; off; off >>= 1) s += __shfl_xor_sync(0xffffffffu, s, off);
            if (lane == 0) g_s[wrp * 4 + r] = s;
        }
        __syncthreads();

        // Gate activations (8 threads, one h-index each)
        if (tid < 8) {
            float gi = xp_s[0 * 8 + tid] + g_s[0 * 8 + tid];
            float gf = xp_s[1 * 8 + tid] + g_s[1 * 8 + tid];
            float gg = xp_s[2 * 8 + tid] + g_s[2 * 8 + tid];
            float go = xp_s[3 * 8 + tid] + g_s[3 * 8 + tid];
            float i_ = 1.f / (1.f + expf(-gi));
            float f_ = 1.f / (1.f + expf(-gf));
            float g_ = tanhf(gg);
            float o_ = 1.f / (1.f + expf(-go));
            c_reg = f_ * c_reg + i_ * g_;
            float h_new = o_ * tanhf(c_reg);
            Hout[(size_t)t * HDIM + hb + tid] = h_new;
            if (t == T_STEPS - 1) {
                if (out_h) out_h[hb + tid] = h_new;
                if (out_c) out_c[hb + tid] = c_reg;
            }
            __threadfence();   // publish h before barrier arrival
        }
        __syncthreads();

        // Grid barrier (all 128 CTAs co-resident; per-step counter, monotonic)
        if (tid == 0) {
            __threadfence();
            unsigned v = atomicAdd(&g_bar[t], 1u) + 1u;
            if (v < (unsigned)NCTA) {
                while (((volatile unsigned*)g_bar)[t] < (unsigned)NCTA) { }
            }
            __threadfence();
        }
        __syncthreads();

        // Reload full h(t) for next step
        ((float4*)h_s)[tid] = ((const float4*)(Hout + (size_t)t * HDIM))[tid];
        __syncthreads();
    }
}

// ---------------------------------------------------------------------------
// Launch
// ---------------------------------------------------------------------------
extern "C" void kernel_launch(void* const* d_in, const int* in_sizes, int n_in,
                              void* d_out, int out_size) {
    const int*   x    = (const int*)  d_in[0];
    const float* emb  = (const float*)d_in[1];
    const float* W_ih = (const float*)d_in[2];   // [2,4096,1024]
    const float* W_hh = (const float*)d_in[3];   // [2,4096,1024]
    const float* b_ih = (const float*)d_in[4];   // [2,4096]
    const float* b_hh = (const float*)d_in[5];   // [2,4096]
    const float* W_fc = (const float*)d_in[6];   // [32000,1024]
    const float* b_fc = (const float*)d_in[7];   // [32000]

    float* out        = (float*)d_out;
    float* out_scores = out;                                   // [512,32000]
    const size_t SC   = (size_t)T_STEPS * VOCAB;               // 16,384,000
    bool  has_state   = ((size_t)out_size >= SC + 4096);
    float* out_h      = has_state ? out + SC        : nullptr; // [2,1024]
    float* out_c      = has_state ? out + SC + 2048 : nullptr; // [2,1024]

    // Device addresses of scratch globals
    void *p_seq, *p_X, *p_H0, *p_H1;
    cudaGetSymbolAddress(&p_seq, g_seq);
    cudaGetSymbolAddress(&p_X,   g_X);
    cudaGetSymbolAddress(&p_H0,  g_H0);
    cudaGetSymbolAddress(&p_H1,  g_H1);
    float* seq = (float*)p_seq;
    float* X   = (float*)p_X;
    float* H0  = (float*)p_H0;
    float* H1  = (float*)p_H1;

    cudaFuncSetAttribute(lstm_recur_kernel,
                         cudaFuncAttributeMaxDynamicSharedMemorySize, RECUR_SMEM);

    const size_t WSZ = (size_t)GDIM * HDIM;   // per-layer weight matrix elems

    // 1) embeddings
    embed_kernel<<<T_STEPS, 256>>>(x, emb);

    // 2) X = seq @ W_ih0^T + b_ih0 + b_hh0
    gemm_nt_bias<<<dim3(GDIM / 128, T_STEPS / 128), 256>>>(
        seq, W_ih, b_ih, b_hh, X, T_STEPS, GDIM, HDIM);

    // 3) layer-0 recurrence
    reset_bar_kernel<<<1, T_STEPS>>>();
    lstm_recur_kernel<<<NCTA, 256, RECUR_SMEM>>>(X, W_hh, H0, out_h, out_c);

    // 4) X = H0 @ W_ih1^T + b_ih1 + b_hh1
    gemm_nt_bias<<<dim3(GDIM / 128, T_STEPS / 128), 256>>>(
        H0, W_ih + WSZ, b_ih + GDIM, b_hh + GDIM, X, T_STEPS, GDIM, HDIM);

    // 5) layer-1 recurrence
    reset_bar_kernel<<<1, T_STEPS>>>();
    lstm_recur_kernel<<<NCTA, 256, RECUR_SMEM>>>(X, W_hh + WSZ, H1,
                                                 out_h ? out_h + HDIM : nullptr,
                                                 out_c ? out_c + HDIM : nullptr);

    // 6) scores = H1 @ W_fc^T + b_fc
    gemm_nt_bias<<<dim3(VOCAB / 128, T_STEPS / 128), 256>>>(
        H1, W_fc, b_fc, nullptr, out_scores, T_STEPS, VOCAB, HDIM);
}

// round 4
// speedup vs baseline: 1.0891x; 1.0891x over previous
#include <cuda_runtime.h>
#include <cuda_bf16.h>
#include <math.h>

// ---------------------------------------------------------------------------
// Problem constants
// ---------------------------------------------------------------------------
#define T_STEPS 512          // L*N = 64*8
#define HDIM    1024
#define GDIM    4096         // 4*H
#define VOCAB   32000
#define NCTA    128          // recurrence CTAs (<= 148 SMs, 1+ CTA/SM -> co-resident)

// ---------------------------------------------------------------------------
// Device scratch (static allocation allowed; cudaMalloc is not)
// ---------------------------------------------------------------------------
__device__ float    g_seq[T_STEPS * HDIM];     // 2 MB  embedding sequence
__device__ float    g_X  [T_STEPS * GDIM];     // 8 MB  precomputed W_ih@x + biases
__device__ float    g_H0 [T_STEPS * HDIM];     // 2 MB  layer-0 hidden states
__device__ float    g_H1 [T_STEPS * HDIM];     // 2 MB  layer-1 hidden states
__device__ unsigned g_bar[T_STEPS];            // per-step grid-barrier counters

// ---------------------------------------------------------------------------
// f32x2 packed-FMA helpers (sm_100+)
// ---------------------------------------------------------------------------
__device__ __forceinline__ unsigned long long pack2(float lo, float hi) {
    unsigned long long r;
    asm("mov.b64 %0, {%1, %2};" : "=l"(r) : "f"(lo), "f"(hi));
    return r;
}
__device__ __forceinline__ void unpack2(unsigned long long v, float& lo, float& hi) {
    asm("mov.b64 {%0, %1}, %2;" : "=f"(lo), "=f"(hi) : "l"(v));
}
__device__ __forceinline__ unsigned long long fma2(unsigned long long a,
                                                   unsigned long long b,
                                                   unsigned long long c) {
    unsigned long long d;
    asm("fma.rn.f32x2 %0, %1, %2, %3;" : "=l"(d) : "l"(a), "l"(b), "l"(c));
    return d;
}

// ---------------------------------------------------------------------------
// Embedding gather: seq[t] = emb[x[n, l]],  t = l*8 + n
// ---------------------------------------------------------------------------
__global__ void embed_kernel(const int* __restrict__ x, const float* __restrict__ emb) {
    int t = blockIdx.x;
    int n = t & 7;
    int l = t >> 3;
    int tok = x[n * 64 + l];
    const float4* src = (const float4*)(emb + (size_t)tok * HDIM);
    ((float4*)(g_seq + (size_t)t * HDIM))[threadIdx.x] = src[threadIdx.x];
}

__global__ void reset_bar_kernel() {
    g_bar[threadIdx.x] = 0u;
}

// ---------------------------------------------------------------------------
// NT GEMM:  C = A @ B^T + bias1 (+ bias2).  128x128x16 tiles, f32x2 FMA.
// ---------------------------------------------------------------------------
__global__ void __launch_bounds__(256, 2) gemm_nt_bias(
    const float* __restrict__ A, const float* __restrict__ B,
    const float* __restrict__ bias1, const float* __restrict__ bias2,
    float* __restrict__ C, int M, int N, int K)
{
    __shared__ float As[16][128];
    __shared__ float Bs[16][128];

    const int tid = threadIdx.x;
    const int tx = tid & 15;
    const int ty = tid >> 4;
    const int bm = blockIdx.y * 128;
    const int bn = blockIdx.x * 128;

    unsigned long long acc[8][4];
    #pragma unroll
    for (int i = 0; i < 8; i++)
        #pragma unroll
        for (int j = 0; j < 4; j++) acc[i][j] = 0ull;

    for (int k0 = 0; k0 < K; k0 += 16) {
        #pragma unroll
        for (int i = 0; i < 2; i++) {
            int chunk = tid * 2 + i;
            int ar = chunk >> 2;
            int ac = chunk & 3;
            float4 v = *(const float4*)(A + (size_t)(bm + ar) * K + k0 + ac * 4);
            As[ac * 4 + 0][ar] = v.x; As[ac * 4 + 1][ar] = v.y;
            As[ac * 4 + 2][ar] = v.z; As[ac * 4 + 3][ar] = v.w;
            float4 u = *(const float4*)(B + (size_t)(bn + ar) * K + k0 + ac * 4);
            Bs[ac * 4 + 0][ar] = u.x; Bs[ac * 4 + 1][ar] = u.y;
            Bs[ac * 4 + 2][ar] = u.z; Bs[ac * 4 + 3][ar] = u.w;
        }
        __syncthreads();

        #pragma unroll
        for (int kk = 0; kk < 16; kk++) {
            float4 a0 = *(const float4*)&As[kk][ty * 8];
            float4 a1 = *(const float4*)&As[kk][ty * 8 + 4];
            const unsigned long long* bp = (const unsigned long long*)&Bs[kk][tx * 8];
            unsigned long long b2[4];
            #pragma unroll
            for (int j = 0; j < 4; j++) b2[j] = bp[j];
            float a[8] = {a0.x, a0.y, a0.z, a0.w, a1.x, a1.y, a1.z, a1.w};
            #pragma unroll
            for (int i = 0; i < 8; i++) {
                unsigned long long a2 = pack2(a[i], a[i]);
                #pragma unroll
                for (int j = 0; j < 4; j++) acc[i][j] = fma2(a2, b2[j], acc[i][j]);
            }
        }
        __syncthreads();
    }

    #pragma unroll
    for (int i = 0; i < 8; i++) {
        int m = bm + ty * 8 + i;
        float* crow = C + (size_t)m * N + bn + tx * 8;
        #pragma unroll
        for (int j = 0; j < 4; j++) {
            float lo, hi;
            unpack2(acc[i][j], lo, hi);
            int n = bn + tx * 8 + 2 * j;
            lo += bias1[n];
            hi += bias1[n + 1];
            if (bias2) { lo += bias2[n]; hi += bias2[n + 1]; }
            *(float2*)(crow + 2 * j) = make_float2(lo, hi);
        }
    }
}

// ---------------------------------------------------------------------------
// LSTM recurrence, register-resident weights.
// 128 CTAs x 256 threads (8 warps). CTA c owns h-indices [8c, 8c+8) = 32 rows.
// lane r = row rr (0..31, rr = gate*8+k); warp w = h-chunk [128w, 128w+128).
// Each thread holds its 128 W_hh weights in registers as 64 f32x2 pairs.
// Per step: broadcast-read h from SMEM (32 LDS.128/thread), 64 fma2/thread,
// cross-warp reduce via padded SMEM, activations on 8 threads, grid barrier.
// ---------------------------------------------------------------------------
__global__ void __launch_bounds__(256) lstm_recur_kernel(
    const float* __restrict__ Xpre,      // [512*4096] ih part + both biases
    const float* __restrict__ Whh,       // [4096*1024]
    float* __restrict__ Hout,            // [512*1024]
    float* __restrict__ out_h,           // [1024] or null
    float* __restrict__ out_c)           // [1024] or null
{
    __shared__ float h_s[HDIM];              // current hidden state
    __shared__ float part_s[32 * 9];         // partials, stride 9 (bank-conflict-free)
    __shared__ float xp_s[32];               // current step's X values for this CTA

    const int tid  = threadIdx.x;
    const int cta  = blockIdx.x;             // 0..127
    const int hb   = cta * 8;
    const int lane = tid & 31;               // row rr
    const int wrp  = tid >> 5;               // h-chunk

    // Row rr -> global row gate*1024 + hb + k   (rr = gate*8 + k)
    const int gate = lane >> 3, k = lane & 7;
    const float* wrow = Whh + (size_t)(gate * 1024 + hb + k) * HDIM + wrp * 128;

    // Load 128 weights into registers as 64 packed f32x2
    unsigned long long w2[64];
    #pragma unroll
    for (int i = 0; i < 32; i++) {
        float4 v = ((const float4*)wrow)[i];
        w2[2 * i]     = pack2(v.x, v.y);
        w2[2 * i + 1] = pack2(v.z, v.w);
    }

    // init h = 0
    ((float4*)h_s)[tid] = make_float4(0.f, 0.f, 0.f, 0.f);
    float c_reg = 0.f;

    // Preload X[0] for this CTA (tid<32: rr = tid)
    float x_next = 0.f;
    if (tid < 32)
        x_next = Xpre[(tid >> 3) * 1024 + hb + (tid & 7)];
    __syncthreads();

    const float4* h4 = (const float4*)h_s;

    for (int t = 0; t < T_STEPS; t++) {
        // publish this step's X, prefetch next step's
        if (tid < 32) {
            xp_s[tid] = x_next;
            if (t + 1 < T_STEPS)
                x_next = Xpre[(size_t)(t + 1) * GDIM + (tid >> 3) * 1024 + hb + (tid & 7)];
        }

        // matvec chunk: dot(W_row[128w..], h[128w..]) with 4 accumulators
        unsigned long long a0 = 0ull, a1 = 0ull, a2 = 0ull, a3 = 0ull;
        #pragma unroll
        for (int i = 0; i < 32; i += 2) {
            float4 hv0 = h4[wrp * 32 + i];
            float4 hv1 = h4[wrp * 32 + i + 1];
            a0 = fma2(w2[2 * i],     pack2(hv0.x, hv0.y), a0);
            a1 = fma2(w2[2 * i + 1], pack2(hv0.z, hv0.w), a1);
            a2 = fma2(w2[2 * i + 2], pack2(hv1.x, hv1.y), a2);
            a3 = fma2(w2[2 * i + 3], pack2(hv1.z, hv1.w), a3);
        }
        float l0, h0, l1, h1, l2, h2, l3, h3;
        unpack2(a0, l0, h0); unpack2(a1, l1, h1);
        unpack2(a2, l2, h2); unpack2(a3, l3, h3);
        part_s[lane * 9 + wrp] = ((l0 + h0) + (l1 + h1)) + ((l2 + h2) + (l3 + h3));
        __syncthreads();

        // activations: thread k (0..7) handles h-index hb+k
        if (tid < 8) {
            float s[4];
            #pragma unroll
            for (int g = 0; g < 4; g++) {
                int rr = g * 8 + tid;
                float v = xp_s[rr];
                #pragma unroll
                for (int w = 0; w < 8; w++) v += part_s[rr * 9 + w];
                s[g] = v;
            }
            float i_ = 1.f / (1.f + __expf(-s[0]));
            float f_ = 1.f / (1.f + __expf(-s[1]));
            float g_ = tanhf(s[2]);
            float o_ = 1.f / (1.f + __expf(-s[3]));
            c_reg = f_ * c_reg + i_ * g_;
            float h_new = o_ * tanhf(c_reg);
            Hout[(size_t)t * HDIM + hb + tid] = h_new;
            if (t == T_STEPS - 1) {
                if (out_h) out_h[hb + tid] = h_new;
                if (out_c) out_c[hb + tid] = c_reg;
            }
            __threadfence();   // publish h before barrier arrival
        }
        __syncthreads();

        // grid barrier (all 128 CTAs co-resident; per-step counter)
        if (tid == 0) {
            unsigned v = atomicAdd(&g_bar[t], 1u) + 1u;
            if (v < (unsigned)NCTA) {
                while (((volatile unsigned*)g_bar)[t] < (unsigned)NCTA) { }
            }
            __threadfence();
        }
        __syncthreads();

        // reload full h(t)
        ((float4*)h_s)[tid] = ((const float4*)(Hout + (size_t)t * HDIM))[tid];
        __syncthreads();
    }
}

// ---------------------------------------------------------------------------
// Launch
// ---------------------------------------------------------------------------
extern "C" void kernel_launch(void* const* d_in, const int* in_sizes, int n_in,
                              void* d_out, int out_size) {
    const int*   x    = (const int*)  d_in[0];
    const float* emb  = (const float*)d_in[1];
    const float* W_ih = (const float*)d_in[2];
    const float* W_hh = (const float*)d_in[3];
    const float* b_ih = (const float*)d_in[4];
    const float* b_hh = (const float*)d_in[5];
    const float* W_fc = (const float*)d_in[6];
    const float* b_fc = (const float*)d_in[7];

    float* out        = (float*)d_out;
    float* out_scores = out;
    const size_t SC   = (size_t)T_STEPS * VOCAB;
    bool  has_state   = ((size_t)out_size >= SC + 4096);
    float* out_h      = has_state ? out + SC        : nullptr;
    float* out_c      = has_state ? out + SC + 2048 : nullptr;

    void *p_seq, *p_X, *p_H0, *p_H1;
    cudaGetSymbolAddress(&p_seq, g_seq);
    cudaGetSymbolAddress(&p_X,   g_X);
    cudaGetSymbolAddress(&p_H0,  g_H0);
    cudaGetSymbolAddress(&p_H1,  g_H1);
    float* seq = (float*)p_seq;
    float* X   = (float*)p_X;
    float* H0  = (float*)p_H0;
    float* H1  = (float*)p_H1;

    const size_t WSZ = (size_t)GDIM * HDIM;

    embed_kernel<<<T_STEPS, 256>>>(x, emb);

    gemm_nt_bias<<<dim3(GDIM / 128, T_STEPS / 128), 256>>>(
        seq, W_ih, b_ih, b_hh, X, T_STEPS, GDIM, HDIM);

    reset_bar_kernel<<<1, T_STEPS>>>();
    lstm_recur_kernel<<<NCTA, 256>>>(X, W_hh, H0, out_h, out_c);

    gemm_nt_bias<<<dim3(GDIM / 128, T_STEPS / 128), 256>>>(
        H0, W_ih + WSZ, b_ih + GDIM, b_hh + GDIM, X, T_STEPS, GDIM, HDIM);

    reset_bar_kernel<<<1, T_STEPS>>>();
    lstm_recur_kernel<<<NCTA, 256>>>(X, W_hh + WSZ, H1,
                                     out_h ? out_h + HDIM : nullptr,
                                     out_c ? out_c + HDIM : nullptr);

    gemm_nt_bias<<<dim3(VOCAB / 128, T_STEPS / 128), 256>>>(
        H1, W_fc, b_fc, nullptr, out_scores, T_STEPS, VOCAB, HDIM);
}